// round 1
// baseline (speedup 1.0000x reference)
#include <cuda_runtime.h>
#include <cstdint>

// Problem constants
#define NN 20000
#define CC 64
#define II 16
#define KK2 120
#define KK1 8
#define KK0 4

// Precomputed per-channel CG tensors (device scratch; no allocation allowed)
// g_W2 layout: [c][x][i][y]  (reordered so the i-contraction vectorizes over y pairs)
__device__ float g_W2[CC * II * II * II];   // 1 MB
__device__ float g_C1[CC * II * II];        // [c][x][y]
__device__ float g_C0[CC * II];             // [c][i]

// ---------------- packed f32x2 helpers ----------------
__device__ __forceinline__ unsigned long long fma2(unsigned long long a,
                                                   unsigned long long b,
                                                   unsigned long long c) {
    unsigned long long d;
    asm("fma.rn.f32x2 %0, %1, %2, %3;" : "=l"(d) : "l"(a), "l"(b), "l"(c));
    return d;
}
__device__ __forceinline__ unsigned long long dup2(float x) {
    unsigned long long d;
    asm("mov.b64 %0, {%1, %1};" : "=l"(d) : "f"(x));
    return d;
}
__device__ __forceinline__ unsigned long long pack2(float lo, float hi) {
    unsigned long long d;
    asm("mov.b64 %0, {%1, %2};" : "=l"(d) : "f"(lo), "f"(hi));
    return d;
}
__device__ __forceinline__ float2 unpack2(unsigned long long v) {
    float2 r;
    asm("mov.b64 {%0, %1}, %2;" : "=f"(r.x), "=f"(r.y) : "l"(v));
    return r;
}
// 128-bit shared load -> two packed f32x2 registers
__device__ __forceinline__ void lds2(unsigned long long& a, unsigned long long& b,
                                     unsigned addr) {
    asm("ld.shared.v2.u64 {%0, %1}, [%2];" : "=l"(a), "=l"(b) : "r"(addr));
}

// ---------------- precompute W2 = U2 . w2  (GEMM 4096x64x120, reordered) ----------------
// grid 64 blocks x 256 threads; block b handles output rows [b*64, b*64+64)
// output row r enumerates (x,i,y):  r = x*256 + i*16 + y
__global__ void __launch_bounds__(256) precomp_w2_kernel(const float* __restrict__ U2,
                                                         const float* __restrict__ w2) {
    __shared__ float sw[KK2 * CC];  // 30720 B
    int t = threadIdx.x;
    for (int j = t; j < KK2 * CC; j += 256) sw[j] = w2[j];
    __syncthreads();

    int lr = t >> 2;            // 0..63 local row
    int q  = t & 3;             // 0..3
    int c0 = q * 16;
    int r  = blockIdx.x * 64 + lr;
    int x = r >> 8, i = (r >> 4) & 15, y = r & 15;
    int u2row = (x * 16 + y) * 16 + i;      // U2 is [x][y][i][k]
    const float* u2p = U2 + (size_t)u2row * KK2;

    float acc[16];
#pragma unroll
    for (int cc = 0; cc < 16; cc++) acc[cc] = 0.f;

    for (int k = 0; k < KK2; k++) {
        float u = u2p[k];
        const float4* wr = (const float4*)(&sw[k * CC + c0]);
        float4 a = wr[0], b = wr[1], cvec = wr[2], d = wr[3];
        acc[0]  = fmaf(u, a.x, acc[0]);  acc[1]  = fmaf(u, a.y, acc[1]);
        acc[2]  = fmaf(u, a.z, acc[2]);  acc[3]  = fmaf(u, a.w, acc[3]);
        acc[4]  = fmaf(u, b.x, acc[4]);  acc[5]  = fmaf(u, b.y, acc[5]);
        acc[6]  = fmaf(u, b.z, acc[6]);  acc[7]  = fmaf(u, b.w, acc[7]);
        acc[8]  = fmaf(u, cvec.x, acc[8]);  acc[9]  = fmaf(u, cvec.y, acc[9]);
        acc[10] = fmaf(u, cvec.z, acc[10]); acc[11] = fmaf(u, cvec.w, acc[11]);
        acc[12] = fmaf(u, d.x, acc[12]); acc[13] = fmaf(u, d.y, acc[13]);
        acc[14] = fmaf(u, d.z, acc[14]); acc[15] = fmaf(u, d.w, acc[15]);
    }
#pragma unroll
    for (int cc = 0; cc < 16; cc++)
        g_W2[(size_t)(c0 + cc) * 4096 + r] = acc[cc];
}

// ---------------- precompute C1, C0 ----------------
__global__ void __launch_bounds__(256) precomp_c1c0_kernel(const float* __restrict__ U1,
                                                           const float* __restrict__ w1,
                                                           const float* __restrict__ U0,
                                                           const float* __restrict__ w0) {
    int tid = blockIdx.x * 256 + threadIdx.x;
    if (tid < CC * II * II) {
        int c = tid & 63;
        int r = tid >> 6;                 // x*16 + y
        float acc = 0.f;
#pragma unroll
        for (int k = 0; k < KK1; k++)
            acc = fmaf(U1[r * KK1 + k], w1[k * CC + c], acc);
        g_C1[c * 256 + r] = acc;
    } else if (tid < CC * II * II + CC * II) {
        int j = tid - CC * II * II;
        int c = j & 63;
        int i = j >> 6;
        float acc = 0.f;
#pragma unroll
        for (int k = 0; k < KK0; k++)
            acc = fmaf(U0[i * KK0 + k], w0[k * CC + c], acc);
        g_C0[c * 16 + i] = acc;
    }
}

// ---------------- main contraction: one thread per (n, c) ----------------
__global__ void __launch_bounds__(128, 4) contract_kernel(const float* __restrict__ nf,
                                                          float* __restrict__ out) {
    __shared__ __align__(16) float sW2[4096];
    __shared__ __align__(16) float sC1[256];
    __shared__ float sC0[16];

    int c = blockIdx.y;
    for (int j = threadIdx.x; j < 4096; j += 128) sW2[j] = g_W2[(size_t)c * 4096 + j];
    for (int j = threadIdx.x; j < 256; j += 128)  sC1[j] = g_C1[c * 256 + j];
    if (threadIdx.x < 16) sC0[threadIdx.x] = g_C0[c * 16 + threadIdx.x];
    __syncthreads();

    unsigned sW2a = (unsigned)__cvta_generic_to_shared(sW2);
    unsigned sC1a = (unsigned)__cvta_generic_to_shared(sC1);

    for (int n = blockIdx.x * 128 + threadIdx.x; n < NN; n += gridDim.x * 128) {
        const float4* fp = (const float4*)(nf + ((size_t)n * CC + c) * II);
        float4 v0 = fp[0], v1 = fp[1], v2 = fp[2], v3 = fp[3];
        float f[16] = {v0.x, v0.y, v0.z, v0.w, v1.x, v1.y, v1.z, v1.w,
                       v2.x, v2.y, v2.z, v2.w, v3.x, v3.y, v3.z, v3.w};
        unsigned long long fd[16];
#pragma unroll
        for (int i = 0; i < 16; i++) fd[i] = dup2(f[i]);
        unsigned long long fp2[8];
#pragma unroll
        for (int p = 0; p < 8; p++) fp2[p] = pack2(f[2 * p], f[2 * p + 1]);

        float acc = 0.f;
#pragma unroll 1
        for (int x = 0; x < 16; x++) {
            unsigned long long A[8];
            unsigned ca = sC1a + x * 64;
            lds2(A[0], A[1], ca);
            lds2(A[2], A[3], ca + 16);
            lds2(A[4], A[5], ca + 32);
            lds2(A[6], A[7], ca + 48);
            unsigned wb = sW2a + x * 1024;
#pragma unroll
            for (int i = 0; i < 16; i++) {
                unsigned long long w0_, w1_, w2_, w3_, w4_, w5_, w6_, w7_;
                unsigned a = wb + i * 64;
                lds2(w0_, w1_, a);
                lds2(w2_, w3_, a + 16);
                lds2(w4_, w5_, a + 32);
                lds2(w6_, w7_, a + 48);
                A[0] = fma2(w0_, fd[i], A[0]);
                A[1] = fma2(w1_, fd[i], A[1]);
                A[2] = fma2(w2_, fd[i], A[2]);
                A[3] = fma2(w3_, fd[i], A[3]);
                A[4] = fma2(w4_, fd[i], A[4]);
                A[5] = fma2(w5_, fd[i], A[5]);
                A[6] = fma2(w6_, fd[i], A[6]);
                A[7] = fma2(w7_, fd[i], A[7]);
            }
            unsigned long long t2 = 0ULL;
#pragma unroll
            for (int p = 0; p < 8; p++) t2 = fma2(A[p], fp2[p], t2);
            float2 tt = unpack2(t2);
            acc = fmaf(sC0[x] + tt.x + tt.y, f[x], acc);
        }
        out[(size_t)n * CC + c] = acc;
    }
}

extern "C" void kernel_launch(void* const* d_in, const int* in_sizes, int n_in,
                              void* d_out, int out_size) {
    const float* nf = (const float*)d_in[0];
    const float* U2 = (const float*)d_in[1];
    const float* U1 = (const float*)d_in[2];
    const float* U0 = (const float*)d_in[3];
    const float* w2 = (const float*)d_in[4];
    const float* w1 = (const float*)d_in[5];
    const float* w0 = (const float*)d_in[6];
    float* out = (float*)d_out;

    precomp_w2_kernel<<<64, 256>>>(U2, w2);
    precomp_c1c0_kernel<<<68, 256>>>(U1, w1, U0, w0);

    dim3 grid(20, CC);
    contract_kernel<<<grid, 128>>>(nf, out);
}

// round 7
// speedup vs baseline: 1.6158x; 1.6158x over previous
#include <cuda_runtime.h>
#include <cstdint>

#define NN 20000
#define CC 64
#define II 16
#define KK2 120
#define KK1 8
#define KK0 4

#define TPC 4                 // 128-atom tiles per CTA
#define QS 164                // Q row stride in floats (conflict-free)
#define SQ_FLOATS (128 * QS)  // 20992
#define SF_OFF SQ_FLOATS
#define SMEM_FLOATS (SQ_FLOATS + 128 * 20)
#define SMEM_BYTES (SMEM_FLOATS * 4)   // 94208

// scratch (device globals; no allocation allowed)
__device__ float g_W2[CC * 4096];            // [c][x*256+y*16+i] = sum_k U2*w2
__device__ float g_Vfrag[CC * 32 * 20 * 4];  // per-lane B fragments, tf32-rounded

// ---------------- helpers ----------------
struct PYI { int y, i; };
__host__ __device__ constexpr PYI pairOf(int p) {
    int y = 0, c = 16;
    while (p >= c) { p -= c; ++y; --c; }
    return {y, y + p};
}

__device__ __forceinline__ uint32_t tf32u(float x) {
    uint32_t u; asm("cvt.rna.tf32.f32 %0, %1;" : "=r"(u) : "f"(x)); return u;
}
__device__ __forceinline__ void ldsv2(uint32_t& a, uint32_t& b, unsigned addr) {
    asm volatile("ld.shared.v2.b32 {%0,%1}, [%2];" : "=r"(a), "=r"(b) : "r"(addr));
}
__device__ __forceinline__ void mma8(float (&d)[4], uint32_t a0, uint32_t a1,
                                     uint32_t a2, uint32_t a3, uint32_t b0,
                                     uint32_t b1) {
    asm volatile(
        "mma.sync.aligned.m16n8k8.row.col.f32.tf32.tf32.f32 "
        "{%0,%1,%2,%3},{%4,%5,%6,%7},{%8,%9},{%0,%1,%2,%3};"
        : "+f"(d[0]), "+f"(d[1]), "+f"(d[2]), "+f"(d[3])
        : "r"(a0), "r"(a1), "r"(a2), "r"(a3), "r"(b0), "r"(b1));
}

// feature value for compile-time index Q
template <int Q>
__device__ __forceinline__ float qv(const float (&f)[16]) {
    if constexpr (Q == 0) return 1.0f;
    else if constexpr (Q <= 16) return f[Q - 1];
    else if constexpr (Q < 153) {
        constexpr PYI pr = pairOf(Q - 17);
        return f[pr.y] * f[pr.i];
    } else return 0.0f;
}

// store Q row tf32-rounded in fragment-permuted order:
// within each 8-col block, position order is [0,4,1,5,2,6,3,7] so that the
// A-fragment pair (col k, col k+4) is contiguous -> ld.shared.v2
template <int CH>
__device__ __forceinline__ void qstore(const float (&f)[16], unsigned addrbase) {
    if constexpr (CH < 40) {
        constexpr int s = CH >> 1, h = CH & 1;
        uint32_t a = tf32u(qv<s * 8 + h * 2 + 0>(f));
        uint32_t b = tf32u(qv<s * 8 + h * 2 + 4>(f));
        uint32_t c = tf32u(qv<s * 8 + h * 2 + 1>(f));
        uint32_t d = tf32u(qv<s * 8 + h * 2 + 5>(f));
        asm volatile("st.shared.v4.b32 [%0], {%1,%2,%3,%4};"
                     :: "r"(addrbase + CH * 16), "r"(a), "r"(b), "r"(c), "r"(d)
                     : "memory");
        qstore<CH + 1>(f, addrbase);
    }
}

// ---------------- precompute 1: W2 = U2 . w2 (GEMM 4096 x 64 x 120) ----------------
__global__ void __launch_bounds__(256) precompW2(const float* __restrict__ U2,
                                                 const float* __restrict__ w2) {
    __shared__ float sw[KK2 * CC];   // 30720 B
    __shared__ float su[16 * KK2];   // 7680 B
    int t = threadIdx.x;
    for (int j = t; j < KK2 * CC; j += 256) sw[j] = w2[j];
    int r0 = blockIdx.x * 16;
    for (int j = t; j < 16 * KK2; j += 256) su[j] = U2[(size_t)r0 * KK2 + j];
    __syncthreads();

    int lr = t >> 4;   // 0..15 local row
    int cg = t & 15;   // channels cg*4 .. cg*4+3
    float a0 = 0.f, a1 = 0.f, a2 = 0.f, a3 = 0.f;
    const float* up = &su[lr * KK2];
    for (int k = 0; k < KK2; k++) {
        float u = up[k];
        float4 w = *(const float4*)&sw[k * CC + cg * 4];
        a0 = fmaf(u, w.x, a0); a1 = fmaf(u, w.y, a1);
        a2 = fmaf(u, w.z, a2); a3 = fmaf(u, w.w, a3);
    }
    int r = r0 + lr;
    g_W2[(size_t)(cg * 4 + 0) * 4096 + r] = a0;
    g_W2[(size_t)(cg * 4 + 1) * 4096 + r] = a1;
    g_W2[(size_t)(cg * 4 + 2) * 4096 + r] = a2;
    g_W2[(size_t)(cg * 4 + 3) * 4096 + r] = a3;
}

// ---------------- precompute 2: assemble per-lane B fragments ----------------
__device__ __forceinline__ float vval(int c, int x, int q,
                                      const float* U1, const float* w1,
                                      const float* U0, const float* w0) {
    float acc = 0.f;
    if (q == 0) {
#pragma unroll
        for (int k = 0; k < KK0; k++)
            acc = fmaf(U0[x * KK0 + k], w0[k * CC + c], acc);
    } else if (q <= 16) {
        int y = q - 1;
#pragma unroll
        for (int k = 0; k < KK1; k++)
            acc = fmaf(U1[(x * II + y) * KK1 + k], w1[k * CC + c], acc);
    } else if (q < 153) {
        int p = q - 17, y = 0, cnt = 16;
        while (p >= cnt) { p -= cnt; ++y; --cnt; }
        int i = y + p;
        acc = g_W2[(size_t)c * 4096 + x * 256 + y * 16 + i];
        if (i != y) acc += g_W2[(size_t)c * 4096 + x * 256 + i * 16 + y];
    }
    return __uint_as_float(tf32u(acc));
}

__global__ void __launch_bounds__(256) precompVfrag(const float* __restrict__ U1,
                                                    const float* __restrict__ w1,
                                                    const float* __restrict__ U0,
                                                    const float* __restrict__ w0) {
    int gid = blockIdx.x * 256 + threadIdx.x;  // (c, lane, s)
    if (gid >= CC * 32 * 20) return;
    int s = gid % 20;
    int lane = (gid / 20) & 31;
    int c = gid / 640;
    int g = lane >> 2, tg = lane & 3;
    float4 v;
    v.x = vval(c, 0 + g, s * 8 + tg,     U1, w1, U0, w0);   // nt0, b0
    v.y = vval(c, 0 + g, s * 8 + tg + 4, U1, w1, U0, w0);   // nt0, b1
    v.z = vval(c, 8 + g, s * 8 + tg,     U1, w1, U0, w0);   // nt1, b0
    v.w = vval(c, 8 + g, s * 8 + tg + 4, U1, w1, U0, w0);   // nt1, b1
    *(float4*)&g_Vfrag[(size_t)gid * 4] = v;
}

// ---------------- main: warp-MMA contraction ----------------
__global__ void __launch_bounds__(128) contract_mma(const float* __restrict__ nf,
                                                    float* __restrict__ out) {
    extern __shared__ float sm[];
    float* sF = sm + SF_OFF;
    unsigned sqb = (unsigned)__cvta_generic_to_shared(sm);
    int tid = threadIdx.x, lane = tid & 31, wid = tid >> 5;
    int c = blockIdx.y;

    // B fragments for this channel, resident in registers for the whole CTA
    float4 bf[20];
    const float4* vp = (const float4*)(g_Vfrag + (size_t)(c * 32 + lane) * 80);
#pragma unroll
    for (int s = 0; s < 20; s++) bf[s] = vp[s];

    unsigned qrow = sqb + tid * (QS * 4);

    for (int t = 0; t < TPC; t++) {
        int base = (blockIdx.x * TPC + t) * 128;
        int n = base + tid;

        float f[16];
        if (n < NN) {
            const float4* fp = (const float4*)(nf + ((size_t)n * CC + c) * II);
            float4 v0 = fp[0], v1 = fp[1], v2 = fp[2], v3 = fp[3];
            f[0] = v0.x; f[1] = v0.y; f[2] = v0.z; f[3] = v0.w;
            f[4] = v1.x; f[5] = v1.y; f[6] = v1.z; f[7] = v1.w;
            f[8] = v2.x; f[9] = v2.y; f[10] = v2.z; f[11] = v2.w;
            f[12] = v3.x; f[13] = v3.y; f[14] = v3.z; f[15] = v3.w;
        } else {
#pragma unroll
            for (int i = 0; i < 16; i++) f[i] = 0.f;
        }

        // exact fp32 f for the epilogue dot
        *(float4*)&sF[tid * 20 + 0]  = make_float4(f[0], f[1], f[2], f[3]);
        *(float4*)&sF[tid * 20 + 4]  = make_float4(f[4], f[5], f[6], f[7]);
        *(float4*)&sF[tid * 20 + 8]  = make_float4(f[8], f[9], f[10], f[11]);
        *(float4*)&sF[tid * 20 + 12] = make_float4(f[12], f[13], f[14], f[15]);

        // tf32 Q row in fragment-permuted layout
        qstore<0>(f, qrow);
        __syncthreads();

#pragma unroll
        for (int mt = 0; mt < 2; mt++) {
            float d0[4], d1[4];
#pragma unroll
            for (int j = 0; j < 4; j++) { d0[j] = 0.f; d1[j] = 0.f; }

            unsigned ab = sqb + (unsigned)((wid * 32 + mt * 16 + (lane >> 2)) * QS) * 4
                        + (lane & 3) * 8;
#pragma unroll
            for (int s = 0; s < 20; s++) {
                uint32_t a0, a2, a1, a3;
                ldsv2(a0, a2, ab + s * 32);                 // rows g, cols k,k+4
                ldsv2(a1, a3, ab + s * 32 + 8 * QS * 4);    // rows g+8
                mma8(d0, a0, a1, a2, a3,
                     __float_as_uint(bf[s].x), __float_as_uint(bf[s].y));
                mma8(d1, a0, a1, a2, a3,
                     __float_as_uint(bf[s].z), __float_as_uint(bf[s].w));
            }

            // epilogue: out[n] = sum_x t[x] * f[x] (exact fp32 f)
#pragma unroll
            for (int h = 0; h < 2; h++) {
                int r = wid * 32 + mt * 16 + (lane >> 2) + h * 8;
                float2 fa = *(const float2*)&sF[r * 20 + (lane & 3) * 2];
                float2 fb = *(const float2*)&sF[r * 20 + 8 + (lane & 3) * 2];
                float p = d0[h * 2] * fa.x + d0[h * 2 + 1] * fa.y
                        + d1[h * 2] * fb.x + d1[h * 2 + 1] * fb.y;
                p += __shfl_xor_sync(0xffffffffu, p, 1);
                p += __shfl_xor_sync(0xffffffffu, p, 2);
                int atom = base + r;
                if ((lane & 3) == 0 && atom < NN)
                    out[(size_t)atom * CC + c] = p;
            }
        }
        __syncthreads();
    }
}

extern "C" void kernel_launch(void* const* d_in, const int* in_sizes, int n_in,
                              void* d_out, int out_size) {
    const float* nf = (const float*)d_in[0];
    const float* U2 = (const float*)d_in[1];
    const float* U1 = (const float*)d_in[2];
    const float* U0 = (const float*)d_in[3];
    const float* w2 = (const float*)d_in[4];
    const float* w1 = (const float*)d_in[5];
    const float* w0 = (const float*)d_in[6];
    float* out = (float*)d_out;

    cudaFuncSetAttribute(contract_mma, cudaFuncAttributeMaxDynamicSharedMemorySize,
                         SMEM_BYTES);

    precompW2<<<256, 256>>>(U2, w2);
    precompVfrag<<<160, 256>>>(U1, w1, U0, w0);

    dim3 grid(40, CC);
    contract_mma<<<grid, 128, SMEM_BYTES>>>(nf, out);
}

// round 9
// speedup vs baseline: 3.9690x; 2.4564x over previous
#include <cuda_runtime.h>
#include <cuda_fp16.h>
#include <cstdint>

#define NN 20000
#define CC 64
#define II 16
#define KK2 120
#define KK1 8
#define KK0 4

#define TPC 4
#define NS 10                 // k16 steps (K = 160)
#define QSTRIDE 88            // Q row stride in 32-bit words
#define SQW 11264             // Q region size in words
#define SFW 2560              // sF: 128 rows x 20 floats
#define SMEM_BYTES ((SQW + SFW) * 4)   // 55296

// device scratch
__device__ float    g_W2[CC * 4096];        // [c][x*256+y*16+i]
__device__ uint32_t g_VfragH[CC * 32 * 40]; // per-lane fp16x2 B fragments

// ---------------- helpers ----------------
struct PYI { int y, i; };
__host__ __device__ constexpr PYI pairOf(int p) {
    int y = 0, c = 16;
    while (p >= c) { p -= c; ++y; --c; }
    return {y, y + p};
}

__device__ __forceinline__ uint32_t packh2(float lo, float hi) {
    __half2 h = __floats2half2_rn(lo, hi);
    return *(uint32_t*)&h;
}
__device__ __forceinline__ void ldsv2(uint32_t& a, uint32_t& b, unsigned addr) {
    asm volatile("ld.shared.v2.b32 {%0,%1}, [%2];" : "=r"(a), "=r"(b) : "r"(addr));
}
__device__ __forceinline__ void mma16816(float (&d)[4], uint32_t a0, uint32_t a1,
                                         uint32_t a2, uint32_t a3, uint32_t b0,
                                         uint32_t b1) {
    asm volatile(
        "mma.sync.aligned.m16n8k16.row.col.f32.f16.f16.f32 "
        "{%0,%1,%2,%3},{%4,%5,%6,%7},{%8,%9},{%0,%1,%2,%3};"
        : "+f"(d[0]), "+f"(d[1]), "+f"(d[2]), "+f"(d[3])
        : "r"(a0), "r"(a1), "r"(a2), "r"(a3), "r"(b0), "r"(b1));
}

// feature value (plain k-index): 0=const, 1..16=f, 17..152=sym pairs, rest 0
template <int Q>
__device__ __forceinline__ float qv(const float (&f)[16]) {
    if constexpr (Q == 0) return 1.0f;
    else if constexpr (Q <= 16) return f[Q - 1];
    else if constexpr (Q < 153) {
        constexpr PYI pr = pairOf(Q - 17);
        return f[pr.y] * f[pr.i];
    } else return 0.0f;
}

// build 10 fp16 chunks for one row half (H warp-uniform).
// chunk (s,H): k-base B = 16s+4H, words = (B,B+1)(B+8,B+9)(B+2,B+3)(B+10,B+11)
template <int CH, int H>
__device__ __forceinline__ void buildQ(const float (&f)[16], unsigned wb) {
    if constexpr (CH < NS) {
        constexpr int B = 16 * CH + 4 * H;
        uint32_t w0 = packh2(qv<B + 0>(f),  qv<B + 1>(f));
        uint32_t w1 = packh2(qv<B + 8>(f),  qv<B + 9>(f));
        uint32_t w2 = packh2(qv<B + 2>(f),  qv<B + 3>(f));
        uint32_t w3 = packh2(qv<B + 10>(f), qv<B + 11>(f));
        asm volatile("st.shared.v4.b32 [%0], {%1,%2,%3,%4};"
                     :: "r"(wb + CH * 32), "r"(w0), "r"(w1), "r"(w2), "r"(w3)
                     : "memory");
        buildQ<CH + 1, H>(f, wb);
    }
}

// ---------------- precompute 1: W2 = U2 . w2 ----------------
__global__ void __launch_bounds__(256) precompW2(const float* __restrict__ U2,
                                                 const float* __restrict__ w2) {
    __shared__ float sw[KK2 * CC];   // 30720 B
    __shared__ float su[32 * KK2];   // 15360 B
    int t = threadIdx.x;
    for (int j = t; j < KK2 * CC; j += 256) sw[j] = w2[j];
    int r0 = blockIdx.x * 32;
    for (int j = t; j < 32 * KK2; j += 256) su[j] = U2[(size_t)r0 * KK2 + j];
    __syncthreads();

    int lr = t >> 4, cg = t & 15;   // rows r0+lr, r0+lr+16; channels cg*4..+3
    float a[8];
#pragma unroll
    for (int q = 0; q < 8; q++) a[q] = 0.f;
    const float* u0p = &su[lr * KK2];
    const float* u1p = &su[(lr + 16) * KK2];
#pragma unroll 4
    for (int k = 0; k < KK2; k++) {
        float u0 = u0p[k], u1 = u1p[k];
        float4 w = *(const float4*)&sw[k * CC + cg * 4];
        a[0] = fmaf(u0, w.x, a[0]); a[1] = fmaf(u0, w.y, a[1]);
        a[2] = fmaf(u0, w.z, a[2]); a[3] = fmaf(u0, w.w, a[3]);
        a[4] = fmaf(u1, w.x, a[4]); a[5] = fmaf(u1, w.y, a[5]);
        a[6] = fmaf(u1, w.z, a[6]); a[7] = fmaf(u1, w.w, a[7]);
    }
#pragma unroll
    for (int q = 0; q < 4; q++) {
        g_W2[(size_t)(cg * 4 + q) * 4096 + r0 + lr]      = a[q];
        g_W2[(size_t)(cg * 4 + q) * 4096 + r0 + lr + 16] = a[4 + q];
    }
}

// ---------------- precompute 2: per-lane fp16 B fragments ----------------
__device__ __forceinline__ float vval(int c, int x, int q,
                                      const float* U1, const float* w1,
                                      const float* U0, const float* w0) {
    float acc = 0.f;
    if (q == 0) {
#pragma unroll
        for (int k = 0; k < KK0; k++)
            acc = fmaf(U0[x * KK0 + k], w0[k * CC + c], acc);
    } else if (q <= 16) {
        int y = q - 1;
#pragma unroll
        for (int k = 0; k < KK1; k++)
            acc = fmaf(U1[(x * II + y) * KK1 + k], w1[k * CC + c], acc);
    } else if (q < 153) {
        int p = q - 17, y = 0, cnt = 16;
        while (p >= cnt) { p -= cnt; ++y; --cnt; }
        int i = y + p;
        acc = g_W2[(size_t)c * 4096 + x * 256 + y * 16 + i];
        if (i != y) acc += g_W2[(size_t)c * 4096 + x * 256 + i * 16 + y];
    }
    return acc;
}

__global__ void __launch_bounds__(256) precompVfrag(const float* __restrict__ U1,
                                                    const float* __restrict__ w1,
                                                    const float* __restrict__ U0,
                                                    const float* __restrict__ w0) {
    int gid = blockIdx.x * 256 + threadIdx.x;   // word index
    if (gid >= CC * 32 * 40) return;
    int w = gid & 3;
    int s = (gid >> 2) % NS;
    int lane = (gid / 40) & 31;
    int c = gid / 1280;
    int g = lane >> 2, tg = lane & 3;
    int n = g + (w >> 1) * 8;                    // x index
    int kb = s * 16 + 2 * tg + (w & 1) * 8;      // k index (plain)
    float vA = vval(c, n, kb,     U1, w1, U0, w0);
    float vB = vval(c, n, kb + 1, U1, w1, U0, w0);
    g_VfragH[gid] = packh2(vA, vB);
}

// ---------------- main kernel ----------------
__global__ void __launch_bounds__(256, 2) contract_mma(const float* __restrict__ nf,
                                                       float* __restrict__ out) {
    extern __shared__ float sm[];
    float* sF = sm + SQW;
    unsigned sqb = (unsigned)__cvta_generic_to_shared(sm);
    int tid = threadIdx.x;
    int lane = tid & 31, w = tid >> 5;
    int g = lane >> 2, tg = lane & 3;
    int c = blockIdx.y;

    // B fragments: 10 x uint4 per lane, in registers for CTA lifetime
    uint4 bw[NS];
    const uint4* vp = (const uint4*)(g_VfragH + (size_t)(c * 32 + lane) * 40);
#pragma unroll
    for (int s = 0; s < NS; s++) bw[s] = vp[s];

    // loader mapping
    int la = tid >> 1, lh = tid & 1;
    // builder mapping (warp-uniform half)
    int ab = tid & 127, H = tid >> 7;
    unsigned wbq = sqb + (unsigned)(ab * QSTRIDE + ((ab >> 2) & 1) * 4 + H * 4) * 4;
    // MMA A addresses
    unsigned aA = sqb + (unsigned)((16 * w + g) * QSTRIDE + ((g >> 2) & 1) * 4
                                   + tg * 2) * 4;

    int tbase0 = blockIdx.x * TPC * 128;
    float4 pv0 = {0, 0, 0, 0}, pv1 = pv0;
    {
        int n = tbase0 + la;
        if (n < NN) {
            const float4* p = (const float4*)(nf + ((size_t)n * CC + c) * II + lh * 8);
            pv0 = p[0]; pv1 = p[1];
        }
    }

    for (int t = 0; t < TPC; t++) {
        int base = tbase0 + t * 128;
        if (base >= NN) break;

        // stage exact fp32 f
        *(float4*)&sF[la * 20 + lh * 8]     = pv0;
        *(float4*)&sF[la * 20 + lh * 8 + 4] = pv1;
        __syncthreads();

        // build fp16 Q (half row per thread, warp-uniform H)
        {
            float f[16];
            float4 c0 = *(float4*)&sF[ab * 20 + 0];
            float4 c1 = *(float4*)&sF[ab * 20 + 4];
            float4 c2 = *(float4*)&sF[ab * 20 + 8];
            float4 c3 = *(float4*)&sF[ab * 20 + 12];
            f[0] = c0.x; f[1] = c0.y; f[2] = c0.z; f[3] = c0.w;
            f[4] = c1.x; f[5] = c1.y; f[6] = c1.z; f[7] = c1.w;
            f[8] = c2.x; f[9] = c2.y; f[10] = c2.z; f[11] = c2.w;
            f[12] = c3.x; f[13] = c3.y; f[14] = c3.z; f[15] = c3.w;
            if (H == 0) buildQ<0, 0>(f, wbq);
            else        buildQ<0, 1>(f, wbq);
        }
        __syncthreads();

        // prefetch next tile's f
        pv0 = make_float4(0, 0, 0, 0); pv1 = pv0;
        if (t + 1 < TPC) {
            int n = base + 128 + la;
            if (n < NN) {
                const float4* p =
                    (const float4*)(nf + ((size_t)n * CC + c) * II + lh * 8);
                pv0 = p[0]; pv1 = p[1];
            }
        }

        // MMA: warp w handles rows 16w..16w+15
        float dA[4] = {0, 0, 0, 0}, dB[4] = {0, 0, 0, 0};
#pragma unroll
        for (int s = 0; s < NS; s++) {
            uint32_t a0, a2, a1, a3;
            ldsv2(a0, a2, aA + s * 32);
            ldsv2(a1, a3, aA + s * 32 + 8 * QSTRIDE * 4);
            mma16816(dA, a0, a1, a2, a3, bw[s].x, bw[s].y);
            mma16816(dB, a0, a1, a2, a3, bw[s].z, bw[s].w);
        }

        // epilogue: out = sum_x t[x] * f[x] (exact fp32 f)
#pragma unroll
        for (int h = 0; h < 2; h++) {
            int r = 16 * w + g + h * 8;
            float2 fa = *(const float2*)&sF[r * 20 + 2 * tg];
            float2 fb = *(const float2*)&sF[r * 20 + 8 + 2 * tg];
            float p = dA[h * 2] * fa.x + dA[h * 2 + 1] * fa.y
                    + dB[h * 2] * fb.x + dB[h * 2 + 1] * fb.y;
            p += __shfl_xor_sync(0xffffffffu, p, 1);
            p += __shfl_xor_sync(0xffffffffu, p, 2);
            int atom = base + r;
            if (tg == 0 && atom < NN) out[(size_t)atom * CC + c] = p;
        }
        __syncthreads();
    }
}

extern "C" void kernel_launch(void* const* d_in, const int* in_sizes, int n_in,
                              void* d_out, int out_size) {
    const float* nf = (const float*)d_in[0];
    const float* U2 = (const float*)d_in[1];
    const float* U1 = (const float*)d_in[2];
    const float* U0 = (const float*)d_in[3];
    const float* w2 = (const float*)d_in[4];
    const float* w1 = (const float*)d_in[5];
    const float* w0 = (const float*)d_in[6];
    float* out = (float*)d_out;

    cudaFuncSetAttribute(contract_mma, cudaFuncAttributeMaxDynamicSharedMemorySize,
                         SMEM_BYTES);

    precompW2<<<128, 256>>>(U2, w2);
    precompVfrag<<<320, 256>>>(U1, w1, U0, w0);

    dim3 grid(40, CC);
    contract_mma<<<grid, 256, SMEM_BYTES>>>(nf, out);
}